// round 3
// baseline (speedup 1.0000x reference)
#include <cuda_runtime.h>
#include <math.h>

#define BATCH 512
#define NV 6890
#define NBETA 10
#define NJOINT 24

#define ACH 16           // kernelA V-chunks
#define ACH_LEN 431      // ceil(6890/16)

#define CBLK 128         // kernelC threads (= vertices per block)
#define NBCH 32          // kernelC batch-chunks
#define BPB (BATCH/NBCH) // 16 batches per block

__constant__ int c_parents[NJOINT] = {-1,0,0,0,1,2,3,4,5,6,7,8,9,9,9,12,13,14,16,17,18,19,20,21};

// Device scratch (no allocations allowed)
__device__ float  g_part[NJOINT][ACH][33];     // partial joint-regressor sums
__device__ float  g_tot [NJOINT][33];          // reduced joint-regressor sums
__device__ float4 g_A4  [BATCH * NJOINT * 3];  // per-batch A matrices (3x4 rows as float4)

// ---- f32x2 packed-math helpers (sm_10x FFMA2) ------------------------------
__device__ __forceinline__ unsigned long long f2pack(float lo, float hi) {
    unsigned long long r;
    asm("mov.b64 %0, {%1, %2};" : "=l"(r) : "f"(lo), "f"(hi));
    return r;
}
__device__ __forceinline__ void f2unpack(unsigned long long v, float& lo, float& hi) {
    asm("mov.b64 {%0, %1}, %2;" : "=f"(lo), "=f"(hi) : "l"(v));
}
__device__ __forceinline__ unsigned long long ffma2(unsigned long long a,
                                                    unsigned long long b,
                                                    unsigned long long c) {
    unsigned long long d;
    asm("fma.rn.f32x2 %0, %1, %2, %3;" : "=l"(d) : "l"(a), "l"(b), "l"(c));
    return d;
}

// ---------------------------------------------------------------------------
// Kernel A: partial sums of Jr @ [v_template | shapedirs] over a V-chunk.
// grid = (24 joints, ACH chunks), block = 256.
// ---------------------------------------------------------------------------
__global__ void __launch_bounds__(256) kernelA(
    const float* __restrict__ shapedirs,   // [V,3,10]
    const float* __restrict__ v_template,  // [V,3]
    const float* __restrict__ Jr)          // [24,V]
{
    int j = blockIdx.x;
    int c = blockIdx.y;
    int tid = threadIdx.x;

    int v0 = c * ACH_LEN;
    int v1 = min(v0 + ACH_LEN, NV);

    float acc[33];
#pragma unroll
    for (int i = 0; i < 33; i++) acc[i] = 0.f;

    for (int v = v0 + tid; v < v1; v += 256) {
        float wj = Jr[j * NV + v];
        const float2* sd2 = (const float2*)(shapedirs + (size_t)v * 30);
        float sd[30];
#pragma unroll
        for (int q = 0; q < 15; q++) { float2 t2 = sd2[q]; sd[2*q] = t2.x; sd[2*q+1] = t2.y; }
#pragma unroll
        for (int k = 0; k < 3; k++) {
            acc[k * 11] += wj * v_template[v * 3 + k];
#pragma unroll
            for (int l = 0; l < NBETA; l++)
                acc[k * 11 + 1 + l] += wj * sd[k * 10 + l];
        }
    }

#pragma unroll
    for (int i = 0; i < 33; i++) {
#pragma unroll
        for (int o = 16; o > 0; o >>= 1)
            acc[i] += __shfl_xor_sync(0xffffffffu, acc[i], o);
    }

    __shared__ float part[8][33];
    int warp = tid >> 5, lane = tid & 31;
    if (lane == 0) {
#pragma unroll
        for (int i = 0; i < 33; i++) part[warp][i] = acc[i];
    }
    __syncthreads();
    if (tid < 33) {
        float s = 0.f;
#pragma unroll
        for (int ww = 0; ww < 8; ww++) s += part[ww][tid];
        g_part[j][c][tid] = s;
    }
}

// Reduce partials: one block, 792 threads.
__global__ void __launch_bounds__(792) kernelA2()
{
    int t = threadIdx.x;           // t = j*33 + i
    int j = t / 33, i = t % 33;
    float s = 0.f;
#pragma unroll
    for (int c = 0; c < ACH; c++) s += g_part[j][c][i];
    g_tot[j][i] = s;
}

// ---------------------------------------------------------------------------
// Kernel B: per-batch joints, rodrigues, kinematic chain, A matrices.
// One warp per batch element.
// ---------------------------------------------------------------------------
__global__ void __launch_bounds__(32) kernelB(
    const float* __restrict__ betas,      // [B,11]
    const float* __restrict__ body_pose,  // [B,69]
    const float* __restrict__ global_or,  // [B,3]
    float* __restrict__ d_out)            // J_transformed region at offset B*V*3
{
    int b = blockIdx.x;
    int lane = threadIdx.x;

    __shared__ float sB[11];
    __shared__ float sLoc[NJOINT][12];
    __shared__ float sWorld[NJOINT][12];
    __shared__ float sJ[NJOINT][3];

    if (lane < 11) sB[lane] = betas[b * 11 + lane];
    __syncwarp();

    if (lane < NJOINT) {
        int j = lane;
        float s0 = sB[0];
#pragma unroll
        for (int k = 0; k < 3; k++) {
            float val = g_tot[j][k * 11];
#pragma unroll
            for (int l = 0; l < NBETA; l++)
                val += sB[1 + l] * g_tot[j][k * 11 + 1 + l];
            sJ[j][k] = val * s0;
        }
    }
    __syncwarp();

    if (lane < NJOINT) {
        int j = lane;
        float r0, r1, r2;
        if (j == 0) {
            r0 = global_or[b * 3 + 0]; r1 = global_or[b * 3 + 1]; r2 = global_or[b * 3 + 2];
        } else {
            const float* pp = body_pose + b * 69 + (j - 1) * 3;
            r0 = pp[0]; r1 = pp[1]; r2 = pp[2];
        }
        float a0 = r0 + 1e-8f, a1 = r1 + 1e-8f, a2 = r2 + 1e-8f;
        float angle = sqrtf(a0 * a0 + a1 * a1 + a2 * a2);
        float inv = 1.0f / angle;
        float rx = r0 * inv, ry = r1 * inv, rz = r2 * inv;
        float c = cosf(angle), s = sinf(angle), t = 1.f - c;
        sLoc[j][0]  = 1.f - t * (ry * ry + rz * rz);
        sLoc[j][1]  = -s * rz + t * rx * ry;
        sLoc[j][2]  =  s * ry + t * rx * rz;
        sLoc[j][4]  =  s * rz + t * rx * ry;
        sLoc[j][5]  = 1.f - t * (rx * rx + rz * rz);
        sLoc[j][6]  = -s * rx + t * ry * rz;
        sLoc[j][8]  = -s * ry + t * rx * rz;
        sLoc[j][9]  =  s * rx + t * ry * rz;
        sLoc[j][10] = 1.f - t * (rx * rx + ry * ry);
        int p = c_parents[j];
#pragma unroll
        for (int k = 0; k < 3; k++)
            sLoc[j][k * 4 + 3] = (p < 0) ? sJ[j][k] : (sJ[j][k] - sJ[p][k]);
    }
    __syncwarp();

    if (lane < 12) sWorld[0][lane] = sLoc[0][lane];
    __syncwarp();
    for (int j = 1; j < NJOINT; j++) {
        if (lane < 12) {
            int r = lane >> 2, cc = lane & 3;
            int p = c_parents[j];
            float val = sWorld[p][r * 4 + 0] * sLoc[j][0 * 4 + cc]
                      + sWorld[p][r * 4 + 1] * sLoc[j][1 * 4 + cc]
                      + sWorld[p][r * 4 + 2] * sLoc[j][2 * 4 + cc];
            if (cc == 3) val += sWorld[p][r * 4 + 3];
            sWorld[j][lane] = val;
        }
        __syncwarp();
    }

    float* Jout = d_out + (size_t)BATCH * NV * 3;
    if (lane < NJOINT) {
        int j = lane;
        float jx = sJ[j][0], jy = sJ[j][1], jz = sJ[j][2];
        float* Aout = (float*)g_A4 + (size_t)b * 288 + j * 12;
#pragma unroll
        for (int r = 0; r < 3; r++) {
            float m0 = sWorld[j][r * 4 + 0];
            float m1 = sWorld[j][r * 4 + 1];
            float m2 = sWorld[j][r * 4 + 2];
            float m3 = sWorld[j][r * 4 + 3];
            Jout[(size_t)b * NJOINT * 3 + j * 3 + r] = m3;
            Aout[r * 4 + 0] = m0;
            Aout[r * 4 + 1] = m1;
            Aout[r * 4 + 2] = m2;
            Aout[r * 4 + 3] = m3 - (m0 * jx + m1 * jy + m2 * jz);
        }
    }
}

// ---------------------------------------------------------------------------
// Kernel C: fused shape blend + LBS, batch-loop inverted, software-pipelined.
// Ping-pong shared A staging with register prefetch: one barrier per batch,
// no exposed L2 latency.
// ---------------------------------------------------------------------------
__global__ void __launch_bounds__(CBLK) kernelC(
    const float* __restrict__ betas,       // [B,11]
    const float* __restrict__ transl,      // [B,3]
    const float* __restrict__ shapedirs,   // [V,3,10]
    const float* __restrict__ v_template,  // [V,3]
    const float* __restrict__ W,           // [V,24]
    float* __restrict__ out)               // verts [B,V,3]
{
    int tid = threadIdx.x;
    int v = blockIdx.x * CBLK + tid;
    int b0 = blockIdx.y * BPB;
    bool valid = (v < NV);
    int vc = valid ? v : (NV - 1);

    __shared__ float4 sA[2][NJOINT * 3];   // ping-pong A[b]: 72 float4 each
    __shared__ float  sBT[2][14];          // betas[0..10], transl[0..2]

    // --- per-vertex constants (live across the whole b-loop) ---
    float sd[30];
    {
        const float2* sd2 = (const float2*)(shapedirs + (size_t)vc * 30);
#pragma unroll
        for (int q = 0; q < 15; q++) { float2 t2 = sd2[q]; sd[2*q] = t2.x; sd[2*q+1] = t2.y; }
    }
    float vt0 = v_template[vc * 3 + 0];
    float vt1 = v_template[vc * 3 + 1];
    float vt2 = v_template[vc * 3 + 2];

    unsigned long long wp[NJOINT];      // (w,w) packed per joint
    {
        const float4* Wp = (const float4*)(W + (size_t)vc * NJOINT);
#pragma unroll
        for (int q = 0; q < 6; q++) {
            float4 t4 = Wp[q];
            wp[4*q + 0] = f2pack(t4.x, t4.x);
            wp[4*q + 1] = f2pack(t4.y, t4.y);
            wp[4*q + 2] = f2pack(t4.z, t4.z);
            wp[4*q + 3] = f2pack(t4.w, t4.w);
        }
    }

    // --- pipeline prologue: sA[0] <- A[b0], prefetch regs <- A[b0+1] ---
    float4 pfA;                          // threads 0..71
    float  pfS = 0.f;                    // threads 72..85
    bool isA = (tid < 72);
    bool isS = (tid >= 72 && tid < 86);

    if (isA) pfA = g_A4[(size_t)b0 * 72 + tid];
    else if (isS) {
        int k = tid - 72;
        pfS = (k < 11) ? betas[b0 * 11 + k] : transl[b0 * 3 + (k - 11)];
    }
    if (isA) sA[0][tid] = pfA;
    else if (isS) sBT[0][tid - 72] = pfS;

    {
        int b1 = min(b0 + 1, BATCH - 1);
        if (isA) pfA = g_A4[(size_t)b1 * 72 + tid];
        else if (isS) {
            int k = tid - 72;
            pfS = (k < 11) ? betas[b1 * 11 + k] : transl[b1 * 3 + (k - 11)];
        }
    }
    __syncthreads();

    int cur = 0;
    for (int ib = 0; ib < BPB; ib++) {
        int b = b0 + ib;
        const ulonglong2* A2 = (const ulonglong2*)sA[cur];
        const float* BT = sBT[cur];

        // shape blend for this (b, v)
        float be0 = BT[0];
        float p0, p1, p2;
        {
            float q0 = vt0, q1 = vt1, q2 = vt2;
#pragma unroll
            for (int l = 0; l < NBETA; l++) {
                float bl = BT[1 + l];
                q0 = fmaf(bl, sd[l],      q0);
                q1 = fmaf(bl, sd[10 + l], q1);
                q2 = fmaf(bl, sd[20 + l], q2);
            }
            p0 = q0 * be0; p1 = q1 * be0; p2 = q2 * be0;
        }

        // T = sum_n w_n * A_n, packed f32x2 (6 pairs = 12 floats of the 3x4)
        unsigned long long T0 = 0ull, T1 = 0ull, T2 = 0ull,
                           T3 = 0ull, T4 = 0ull, T5 = 0ull;
#pragma unroll
        for (int n = 0; n < NJOINT; n++) {
            ulonglong2 q0 = A2[n * 3 + 0];
            ulonglong2 q1 = A2[n * 3 + 1];
            ulonglong2 q2 = A2[n * 3 + 2];
            unsigned long long w = wp[n];
            T0 = ffma2(w, q0.x, T0); T1 = ffma2(w, q0.y, T1);
            T2 = ffma2(w, q1.x, T2); T3 = ffma2(w, q1.y, T3);
            T4 = ffma2(w, q2.x, T4); T5 = ffma2(w, q2.y, T5);
        }

        if (valid) {
            float t00, t01, t02, t03, t10, t11, t12, t13, t20, t21, t22, t23;
            f2unpack(T0, t00, t01); f2unpack(T1, t02, t03);
            f2unpack(T2, t10, t11); f2unpack(T3, t12, t13);
            f2unpack(T4, t20, t21); f2unpack(T5, t22, t23);
            size_t base = ((size_t)b * NV + v) * 3;
            out[base + 0] = fmaf(t00, p0, fmaf(t01, p1, fmaf(t02, p2, t03 + BT[11])));
            out[base + 1] = fmaf(t10, p0, fmaf(t11, p1, fmaf(t12, p2, t13 + BT[12])));
            out[base + 2] = fmaf(t20, p0, fmaf(t21, p1, fmaf(t22, p2, t23 + BT[13])));
        }

        // stage prefetched A[b+1] into the other buffer, start prefetch of A[b+2]
        int other = cur ^ 1;
        if (isA) sA[other][tid] = pfA;
        else if (isS) sBT[other][tid - 72] = pfS;

        int bn = min(b + 2, BATCH - 1);
        if (isA) pfA = g_A4[(size_t)bn * 72 + tid];
        else if (isS) {
            int k = tid - 72;
            pfS = (k < 11) ? betas[bn * 11 + k] : transl[bn * 3 + (k - 11)];
        }

        __syncthreads();
        cur = other;
    }
}

extern "C" void kernel_launch(void* const* d_in, const int* in_sizes, int n_in,
                              void* d_out, int out_size)
{
    const float* betas      = (const float*)d_in[0];
    const float* body_pose  = (const float*)d_in[1];
    const float* global_or  = (const float*)d_in[2];
    const float* transl     = (const float*)d_in[3];
    const float* shapedirs  = (const float*)d_in[4];
    const float* v_template = (const float*)d_in[5];
    const float* Jr         = (const float*)d_in[6];
    const float* W          = (const float*)d_in[7];
    float* out = (float*)d_out;

    dim3 gridA(NJOINT, ACH);
    kernelA<<<gridA, 256>>>(shapedirs, v_template, Jr);
    kernelA2<<<1, 792>>>();
    kernelB<<<BATCH, 32>>>(betas, body_pose, global_or, out);
    dim3 gridC((NV + CBLK - 1) / CBLK, NBCH);
    kernelC<<<gridC, CBLK>>>(betas, transl, shapedirs, v_template, W, out);
}

// round 4
// speedup vs baseline: 1.0027x; 1.0027x over previous
#include <cuda_runtime.h>
#include <math.h>

#define BATCH 512
#define NV 6890
#define NBETA 10
#define NJOINT 24

#define ATILE 128
#define NBLKA ((NV + ATILE - 1) / ATILE)   // 54

#define CBLK 128         // kernelC threads
#define NBCH 32          // kernelC batch-chunks
#define BPB (BATCH/NBCH) // 16 batches per block

__constant__ int c_parents[NJOINT] = {-1,0,0,0,1,2,3,4,5,6,7,8,9,9,9,12,13,14,16,17,18,19,20,21};

// Device scratch (no allocations allowed)
__device__ float  g_part2[NBLKA][NJOINT][33];  // per-block partial regressor sums (feat order)
__device__ float  g_tot [NJOINT][33];          // reduced sums (kernelB order)
__device__ float4 g_A4  [BATCH * NJOINT * 3];  // per-batch A matrices (3x4 rows as float4)

// ---- f32x2 packed-math helpers --------------------------------------------
__device__ __forceinline__ void f2unpack(unsigned long long v, float& lo, float& hi) {
    asm("mov.b64 {%0, %1}, %2;" : "=f"(lo), "=f"(hi) : "l"(v));
}
__device__ __forceinline__ unsigned long long ffma2(unsigned long long a,
                                                    unsigned long long b,
                                                    unsigned long long c) {
    unsigned long long d;
    asm("fma.rn.f32x2 %0, %1, %2, %3;" : "=l"(d) : "l"(a), "l"(b), "l"(c));
    return d;
}

// ---- cp.async helpers ------------------------------------------------------
__device__ __forceinline__ void cp16(unsigned int dst, const void* src) {
    asm volatile("cp.async.cg.shared.global [%0], [%1], 16;" :: "r"(dst), "l"(src) : "memory");
}
__device__ __forceinline__ void cp_commit() {
    asm volatile("cp.async.commit_group;" ::: "memory");
}
__device__ __forceinline__ void cp_wait1() {
    asm volatile("cp.async.wait_group 1;" ::: "memory");
}
__device__ __forceinline__ void cp_wait0() {
    asm volatile("cp.async.wait_group 0;" ::: "memory");
}

// ---------------------------------------------------------------------------
// Kernel A: block stages a 128-vertex feature tile (vt+shapedirs, 33 comps)
// and the 24x128 Jr tile in smem; 8 warps x 3 joints consume it.
// Writes g_part2[block][j][i] in feat order: i 0..2 = vt, 3..32 = sd(k*10+l).
// ---------------------------------------------------------------------------
__global__ void __launch_bounds__(256) kernelA(
    const float* __restrict__ shapedirs,   // [V,3,10]
    const float* __restrict__ v_template,  // [V,3]
    const float* __restrict__ Jr)          // [24,V]
{
    __shared__ float feat[ATILE][33];
    __shared__ float sJr[NJOINT][ATILE];

    int tid = threadIdx.x;
    int v0 = blockIdx.x * ATILE;

    for (int idx = tid; idx < ATILE * 33; idx += 256) {
        int v = idx / 33, i = idx % 33;
        int gv = v0 + v;
        float val = 0.f;
        if (gv < NV) val = (i < 3) ? v_template[gv * 3 + i]
                                   : shapedirs[(size_t)gv * 30 + (i - 3)];
        feat[v][i] = val;
    }
    for (int idx = tid; idx < NJOINT * ATILE; idx += 256) {
        int j = idx >> 7, v = idx & (ATILE - 1);
        int gv = v0 + v;
        sJr[j][v] = (gv < NV) ? Jr[j * NV + gv] : 0.f;
    }
    __syncthreads();

    int warp = tid >> 5, lane = tid & 31;
#pragma unroll
    for (int jj = 0; jj < 3; jj++) {
        int j = warp * 3 + jj;
        for (int i = lane; i < 33; i += 32) {
            float acc = 0.f;
#pragma unroll 8
            for (int v = 0; v < ATILE; v++)
                acc = fmaf(sJr[j][v], feat[v][i], acc);
            g_part2[blockIdx.x][j][i] = acc;
        }
    }
}

// Reduce partials + remap to kernelB layout. One block, 792 threads.
__global__ void __launch_bounds__(792) kernelA2()
{
    int t = threadIdx.x;           // t = j*33 + i33 (kernelB layout)
    int j = t / 33, i33 = t % 33;
    int src;
    if (i33 % 11 == 0) src = i33 / 11;                 // vt comp k
    else { int k = i33 / 11, l = i33 % 11 - 1; src = 3 + k * 10 + l; }
    float s = 0.f;
    for (int c = 0; c < NBLKA; c++) s += g_part2[c][j][src];
    g_tot[j][i33] = s;
}

// ---------------------------------------------------------------------------
// Kernel B: per-batch joints, rodrigues, kinematic chain, A matrices.
// ---------------------------------------------------------------------------
__global__ void __launch_bounds__(32) kernelB(
    const float* __restrict__ betas,      // [B,11]
    const float* __restrict__ body_pose,  // [B,69]
    const float* __restrict__ global_or,  // [B,3]
    float* __restrict__ d_out)            // J_transformed at offset B*V*3
{
    int b = blockIdx.x;
    int lane = threadIdx.x;

    __shared__ float sB[11];
    __shared__ float sLoc[NJOINT][12];
    __shared__ float sWorld[NJOINT][12];
    __shared__ float sJ[NJOINT][3];

    if (lane < 11) sB[lane] = betas[b * 11 + lane];
    __syncwarp();

    if (lane < NJOINT) {
        int j = lane;
        float s0 = sB[0];
#pragma unroll
        for (int k = 0; k < 3; k++) {
            float val = g_tot[j][k * 11];
#pragma unroll
            for (int l = 0; l < NBETA; l++)
                val += sB[1 + l] * g_tot[j][k * 11 + 1 + l];
            sJ[j][k] = val * s0;
        }
    }
    __syncwarp();

    if (lane < NJOINT) {
        int j = lane;
        float r0, r1, r2;
        if (j == 0) {
            r0 = global_or[b * 3 + 0]; r1 = global_or[b * 3 + 1]; r2 = global_or[b * 3 + 2];
        } else {
            const float* pp = body_pose + b * 69 + (j - 1) * 3;
            r0 = pp[0]; r1 = pp[1]; r2 = pp[2];
        }
        float a0 = r0 + 1e-8f, a1 = r1 + 1e-8f, a2 = r2 + 1e-8f;
        float angle = sqrtf(a0 * a0 + a1 * a1 + a2 * a2);
        float inv = 1.0f / angle;
        float rx = r0 * inv, ry = r1 * inv, rz = r2 * inv;
        float c = cosf(angle), s = sinf(angle), t = 1.f - c;
        sLoc[j][0]  = 1.f - t * (ry * ry + rz * rz);
        sLoc[j][1]  = -s * rz + t * rx * ry;
        sLoc[j][2]  =  s * ry + t * rx * rz;
        sLoc[j][4]  =  s * rz + t * rx * ry;
        sLoc[j][5]  = 1.f - t * (rx * rx + rz * rz);
        sLoc[j][6]  = -s * rx + t * ry * rz;
        sLoc[j][8]  = -s * ry + t * rx * rz;
        sLoc[j][9]  =  s * rx + t * ry * rz;
        sLoc[j][10] = 1.f - t * (rx * rx + ry * ry);
        int p = c_parents[j];
#pragma unroll
        for (int k = 0; k < 3; k++)
            sLoc[j][k * 4 + 3] = (p < 0) ? sJ[j][k] : (sJ[j][k] - sJ[p][k]);
    }
    __syncwarp();

    if (lane < 12) sWorld[0][lane] = sLoc[0][lane];
    __syncwarp();
    for (int j = 1; j < NJOINT; j++) {
        if (lane < 12) {
            int r = lane >> 2, cc = lane & 3;
            int p = c_parents[j];
            float val = sWorld[p][r * 4 + 0] * sLoc[j][0 * 4 + cc]
                      + sWorld[p][r * 4 + 1] * sLoc[j][1 * 4 + cc]
                      + sWorld[p][r * 4 + 2] * sLoc[j][2 * 4 + cc];
            if (cc == 3) val += sWorld[p][r * 4 + 3];
            sWorld[j][lane] = val;
        }
        __syncwarp();
    }

    float* Jout = d_out + (size_t)BATCH * NV * 3;
    if (lane < NJOINT) {
        int j = lane;
        float jx = sJ[j][0], jy = sJ[j][1], jz = sJ[j][2];
        float* Aout = (float*)g_A4 + (size_t)b * 288 + j * 12;
#pragma unroll
        for (int r = 0; r < 3; r++) {
            float m0 = sWorld[j][r * 4 + 0];
            float m1 = sWorld[j][r * 4 + 1];
            float m2 = sWorld[j][r * 4 + 2];
            float m3 = sWorld[j][r * 4 + 3];
            Jout[(size_t)b * NJOINT * 3 + j * 3 + r] = m3;
            Aout[r * 4 + 0] = m0;
            Aout[r * 4 + 1] = m1;
            Aout[r * 4 + 2] = m2;
            Aout[r * 4 + 3] = m3 - (m0 * jx + m1 * jy + m2 * jz);
        }
    }
}

// ---------------------------------------------------------------------------
// Kernel C: fused shape blend + LBS, warp-independent cp.async pipeline.
// Each warp double-buffers A[b] in its own smem region. No block barriers
// in the loop; weights packed (w,w) on the fly (ALU pipe is idle).
// ---------------------------------------------------------------------------
__global__ void __launch_bounds__(CBLK, 6) kernelC(
    const float* __restrict__ betas,       // [B,11]
    const float* __restrict__ transl,      // [B,3]
    const float* __restrict__ shapedirs,   // [V,3,10]
    const float* __restrict__ v_template,  // [V,3]
    const float* __restrict__ W,           // [V,24]
    float* __restrict__ out)               // verts [B,V,3]
{
    __shared__ float4 sAw[CBLK / 32][2][NJOINT * 3];  // per-warp double buffer
    __shared__ float  sBT[BPB][14];                   // betas+transl per batch

    int tid = threadIdx.x;
    int lane = tid & 31;
    int w = tid >> 5;
    int v = blockIdx.x * CBLK + tid;
    int b0 = blockIdx.y * BPB;
    bool valid = (v < NV);
    int vc = valid ? v : (NV - 1);

    // stage betas/transl for the whole batch chunk (once)
    for (int idx = tid; idx < BPB * 14; idx += CBLK) {
        int ib = idx / 14, k = idx % 14;
        sBT[ib][k] = (k < 11) ? betas[(b0 + ib) * 11 + k]
                              : transl[(b0 + ib) * 3 + (k - 11)];
    }

    // --- per-vertex constants ---
    float sd[30];
    {
        const float2* sd2 = (const float2*)(shapedirs + (size_t)vc * 30);
#pragma unroll
        for (int q = 0; q < 15; q++) { float2 t2 = sd2[q]; sd[2*q] = t2.x; sd[2*q+1] = t2.y; }
    }
    float vt0 = v_template[vc * 3 + 0];
    float vt1 = v_template[vc * 3 + 1];
    float vt2 = v_template[vc * 3 + 2];

    float wv[NJOINT];
    {
        const float4* Wp = (const float4*)(W + (size_t)vc * NJOINT);
#pragma unroll
        for (int q = 0; q < 6; q++) {
            float4 t4 = Wp[q];
            wv[4*q] = t4.x; wv[4*q+1] = t4.y; wv[4*q+2] = t4.z; wv[4*q+3] = t4.w;
        }
    }

    // --- cp.async staging: 72 float4 per batch, per warp ---
    unsigned int sbase = (unsigned int)__cvta_generic_to_shared(&sAw[w][0][0]);
    const float4* Ag = g_A4;

    // stage buffer 0 <- b0, buffer 1 <- b0+1
    {
        const float4* s0 = Ag + (size_t)b0 * 72 + lane;
        unsigned int d = sbase + lane * 16;
        cp16(d, s0); cp16(d + 32 * 16, s0 + 32);
        if (lane < 8) cp16(d + 64 * 16, s0 + 64);
        cp_commit();
        const float4* s1 = Ag + (size_t)(b0 + 1) * 72 + lane;
        unsigned int d1 = d + 72 * 16;
        cp16(d1, s1); cp16(d1 + 32 * 16, s1 + 32);
        if (lane < 8) cp16(d1 + 64 * 16, s1 + 64);
        cp_commit();
    }
    __syncthreads();   // sBT visible (does not wait on cp.async)

    for (int ib = 0; ib < BPB; ib++) {
        if (ib >= BPB - 2) cp_wait0(); else cp_wait1();
        __syncwarp();

        int cur = ib & 1;
        const ulonglong2* A2 = (const ulonglong2*)&sAw[w][cur][0];
        const float* BT = sBT[ib];

        // shape blend
        float be0 = BT[0];
        float q0 = vt0, q1 = vt1, q2 = vt2;
#pragma unroll
        for (int l = 0; l < NBETA; l++) {
            float bl = BT[1 + l];
            q0 = fmaf(bl, sd[l],      q0);
            q1 = fmaf(bl, sd[10 + l], q1);
            q2 = fmaf(bl, sd[20 + l], q2);
        }
        float p0 = q0 * be0, p1 = q1 * be0, p2 = q2 * be0;

        // T = sum_n w_n * A_n (packed f32x2, weights packed on the fly)
        unsigned long long T0 = 0ull, T1 = 0ull, T2 = 0ull,
                           T3 = 0ull, T4 = 0ull, T5 = 0ull;
#pragma unroll
        for (int n = 0; n < NJOINT; n++) {
            unsigned long long wpk;
            asm volatile("mov.b64 %0, {%1, %1};" : "=l"(wpk) : "f"(wv[n]));
            ulonglong2 a0 = A2[n * 3 + 0];
            ulonglong2 a1 = A2[n * 3 + 1];
            ulonglong2 a2 = A2[n * 3 + 2];
            T0 = ffma2(wpk, a0.x, T0); T1 = ffma2(wpk, a0.y, T1);
            T2 = ffma2(wpk, a1.x, T2); T3 = ffma2(wpk, a1.y, T3);
            T4 = ffma2(wpk, a2.x, T4); T5 = ffma2(wpk, a2.y, T5);
        }

        if (valid) {
            float t00, t01, t02, t03, t10, t11, t12, t13, t20, t21, t22, t23;
            f2unpack(T0, t00, t01); f2unpack(T1, t02, t03);
            f2unpack(T2, t10, t11); f2unpack(T3, t12, t13);
            f2unpack(T4, t20, t21); f2unpack(T5, t22, t23);
            size_t base = ((size_t)(b0 + ib) * NV + v) * 3;
            out[base + 0] = fmaf(t00, p0, fmaf(t01, p1, fmaf(t02, p2, t03 + BT[11])));
            out[base + 1] = fmaf(t10, p0, fmaf(t11, p1, fmaf(t12, p2, t13 + BT[12])));
            out[base + 2] = fmaf(t20, p0, fmaf(t21, p1, fmaf(t22, p2, t23 + BT[13])));
        }

        // refill the buffer we just consumed with A[b+2]
        if (ib + 2 < BPB) {
            const float4* sn = Ag + (size_t)(b0 + ib + 2) * 72 + lane;
            unsigned int d = sbase + cur * (72 * 16) + lane * 16;
            cp16(d, sn); cp16(d + 32 * 16, sn + 32);
            if (lane < 8) cp16(d + 64 * 16, sn + 64);
            cp_commit();
        }
    }
}

extern "C" void kernel_launch(void* const* d_in, const int* in_sizes, int n_in,
                              void* d_out, int out_size)
{
    const float* betas      = (const float*)d_in[0];
    const float* body_pose  = (const float*)d_in[1];
    const float* global_or  = (const float*)d_in[2];
    const float* transl     = (const float*)d_in[3];
    const float* shapedirs  = (const float*)d_in[4];
    const float* v_template = (const float*)d_in[5];
    const float* Jr         = (const float*)d_in[6];
    const float* W          = (const float*)d_in[7];
    float* out = (float*)d_out;

    kernelA<<<NBLKA, 256>>>(shapedirs, v_template, Jr);
    kernelA2<<<1, 792>>>();
    kernelB<<<BATCH, 32>>>(betas, body_pose, global_or, out);
    dim3 gridC((NV + CBLK - 1) / CBLK, NBCH);
    kernelC<<<gridC, CBLK>>>(betas, transl, shapedirs, v_template, W, out);
}

// round 5
// speedup vs baseline: 1.0260x; 1.0233x over previous
#include <cuda_runtime.h>
#include <math.h>

#define BATCH 512
#define NV 6890
#define NBETA 10
#define NJOINT 24

#define ATILE 64
#define NBLKA ((NV + ATILE - 1) / ATILE)   // 108

#define CBLK 128         // kernelC threads
#define NBCH 32          // kernelC batch-chunks
#define BPB (BATCH/NBCH) // 16 batches per block

__constant__ int c_parents[NJOINT] = {-1,0,0,0,1,2,3,4,5,6,7,8,9,9,9,12,13,14,16,17,18,19,20,21};

// Device scratch (no allocations allowed)
__device__ float  g_part2[NBLKA][NJOINT][33];  // per-block partial regressor sums (feat order)
__device__ float  g_tot [NJOINT][33];          // reduced sums (kernelB order)
__device__ float4 g_A4  [BATCH * NJOINT * 3];  // per-batch A matrices (3x4 rows as float4)

// ---- f32x2 packed-math helpers --------------------------------------------
__device__ __forceinline__ void f2unpack(unsigned long long v, float& lo, float& hi) {
    asm("mov.b64 {%0, %1}, %2;" : "=f"(lo), "=f"(hi) : "l"(v));
}
__device__ __forceinline__ unsigned long long ffma2(unsigned long long a,
                                                    unsigned long long b,
                                                    unsigned long long c) {
    unsigned long long d;
    asm("fma.rn.f32x2 %0, %1, %2, %3;" : "=l"(d) : "l"(a), "l"(b), "l"(c));
    return d;
}

// ---- cp.async helpers ------------------------------------------------------
__device__ __forceinline__ void cp16(unsigned int dst, const void* src) {
    asm volatile("cp.async.cg.shared.global [%0], [%1], 16;" :: "r"(dst), "l"(src) : "memory");
}
__device__ __forceinline__ void cp_commit() {
    asm volatile("cp.async.commit_group;" ::: "memory");
}
__device__ __forceinline__ void cp_wait1() {
    asm volatile("cp.async.wait_group 1;" ::: "memory");
}
__device__ __forceinline__ void cp_wait0() {
    asm volatile("cp.async.wait_group 0;" ::: "memory");
}

// ---------------------------------------------------------------------------
// Kernel A: block stages a 64-vertex feature tile (vt+shapedirs, 33 comps)
// and the 24x64 Jr tile in smem; 8 warps x 3 joints consume it with 4
// independent accumulator chains.
// ---------------------------------------------------------------------------
__global__ void __launch_bounds__(256) kernelA(
    const float* __restrict__ shapedirs,   // [V,3,10]
    const float* __restrict__ v_template,  // [V,3]
    const float* __restrict__ Jr)          // [24,V]
{
    __shared__ float feat[ATILE][33];
    __shared__ float sJr[NJOINT][ATILE];

    int tid = threadIdx.x;
    int v0 = blockIdx.x * ATILE;

    for (int idx = tid; idx < ATILE * 33; idx += 256) {
        int v = idx / 33, i = idx % 33;
        int gv = v0 + v;
        float val = 0.f;
        if (gv < NV) val = (i < 3) ? v_template[gv * 3 + i]
                                   : shapedirs[(size_t)gv * 30 + (i - 3)];
        feat[v][i] = val;
    }
    for (int idx = tid; idx < NJOINT * ATILE; idx += 256) {
        int j = idx / ATILE, v = idx % ATILE;
        int gv = v0 + v;
        sJr[j][v] = (gv < NV) ? Jr[j * NV + gv] : 0.f;
    }
    __syncthreads();

    int warp = tid >> 5, lane = tid & 31;
#pragma unroll
    for (int jj = 0; jj < 3; jj++) {
        int j = warp * 3 + jj;
        for (int i = lane; i < 33; i += 32) {
            float a0 = 0.f, a1 = 0.f, a2 = 0.f, a3 = 0.f;
#pragma unroll
            for (int v = 0; v < ATILE; v += 4) {
                a0 = fmaf(sJr[j][v + 0], feat[v + 0][i], a0);
                a1 = fmaf(sJr[j][v + 1], feat[v + 1][i], a1);
                a2 = fmaf(sJr[j][v + 2], feat[v + 2][i], a2);
                a3 = fmaf(sJr[j][v + 3], feat[v + 3][i], a3);
            }
            g_part2[blockIdx.x][j][i] = (a0 + a1) + (a2 + a3);
        }
    }
}

// Reduce partials + remap to kernelB layout. One block, 792 threads.
__global__ void __launch_bounds__(792) kernelA2()
{
    int t = threadIdx.x;           // t = j*33 + i33 (kernelB layout)
    int j = t / 33, i33 = t % 33;
    int src;
    if (i33 % 11 == 0) src = i33 / 11;                 // vt comp k
    else { int k = i33 / 11, l = i33 % 11 - 1; src = 3 + k * 10 + l; }
    float s0 = 0.f, s1 = 0.f, s2 = 0.f, s3 = 0.f;
    for (int c = 0; c < NBLKA; c += 4) {
        s0 += g_part2[c + 0][j][src];
        s1 += g_part2[c + 1][j][src];
        s2 += g_part2[c + 2][j][src];
        s3 += g_part2[c + 3][j][src];
    }
    g_tot[j][i33] = (s0 + s1) + (s2 + s3);
}

// ---------------------------------------------------------------------------
// Kernel B: per-batch joints, rodrigues, kinematic chain, A matrices.
// ---------------------------------------------------------------------------
__global__ void __launch_bounds__(32) kernelB(
    const float* __restrict__ betas,      // [B,11]
    const float* __restrict__ body_pose,  // [B,69]
    const float* __restrict__ global_or,  // [B,3]
    float* __restrict__ d_out)            // J_transformed at offset B*V*3
{
    int b = blockIdx.x;
    int lane = threadIdx.x;

    __shared__ float sB[11];
    __shared__ float sLoc[NJOINT][12];
    __shared__ float sWorld[NJOINT][12];
    __shared__ float sJ[NJOINT][3];

    if (lane < 11) sB[lane] = betas[b * 11 + lane];
    __syncwarp();

    if (lane < NJOINT) {
        int j = lane;
        float s0 = sB[0];
#pragma unroll
        for (int k = 0; k < 3; k++) {
            float val = g_tot[j][k * 11];
#pragma unroll
            for (int l = 0; l < NBETA; l++)
                val += sB[1 + l] * g_tot[j][k * 11 + 1 + l];
            sJ[j][k] = val * s0;
        }
    }
    __syncwarp();

    if (lane < NJOINT) {
        int j = lane;
        float r0, r1, r2;
        if (j == 0) {
            r0 = global_or[b * 3 + 0]; r1 = global_or[b * 3 + 1]; r2 = global_or[b * 3 + 2];
        } else {
            const float* pp = body_pose + b * 69 + (j - 1) * 3;
            r0 = pp[0]; r1 = pp[1]; r2 = pp[2];
        }
        float a0 = r0 + 1e-8f, a1 = r1 + 1e-8f, a2 = r2 + 1e-8f;
        float angle = sqrtf(a0 * a0 + a1 * a1 + a2 * a2);
        float inv = 1.0f / angle;
        float rx = r0 * inv, ry = r1 * inv, rz = r2 * inv;
        float c = cosf(angle), s = sinf(angle), t = 1.f - c;
        sLoc[j][0]  = 1.f - t * (ry * ry + rz * rz);
        sLoc[j][1]  = -s * rz + t * rx * ry;
        sLoc[j][2]  =  s * ry + t * rx * rz;
        sLoc[j][4]  =  s * rz + t * rx * ry;
        sLoc[j][5]  = 1.f - t * (rx * rx + rz * rz);
        sLoc[j][6]  = -s * rx + t * ry * rz;
        sLoc[j][8]  = -s * ry + t * rx * rz;
        sLoc[j][9]  =  s * rx + t * ry * rz;
        sLoc[j][10] = 1.f - t * (rx * rx + ry * ry);
        int p = c_parents[j];
#pragma unroll
        for (int k = 0; k < 3; k++)
            sLoc[j][k * 4 + 3] = (p < 0) ? sJ[j][k] : (sJ[j][k] - sJ[p][k]);
    }
    __syncwarp();

    if (lane < 12) sWorld[0][lane] = sLoc[0][lane];
    __syncwarp();
    for (int j = 1; j < NJOINT; j++) {
        if (lane < 12) {
            int r = lane >> 2, cc = lane & 3;
            int p = c_parents[j];
            float val = sWorld[p][r * 4 + 0] * sLoc[j][0 * 4 + cc]
                      + sWorld[p][r * 4 + 1] * sLoc[j][1 * 4 + cc]
                      + sWorld[p][r * 4 + 2] * sLoc[j][2 * 4 + cc];
            if (cc == 3) val += sWorld[p][r * 4 + 3];
            sWorld[j][lane] = val;
        }
        __syncwarp();
    }

    float* Jout = d_out + (size_t)BATCH * NV * 3;
    if (lane < NJOINT) {
        int j = lane;
        float jx = sJ[j][0], jy = sJ[j][1], jz = sJ[j][2];
        float* Aout = (float*)g_A4 + (size_t)b * 288 + j * 12;
#pragma unroll
        for (int r = 0; r < 3; r++) {
            float m0 = sWorld[j][r * 4 + 0];
            float m1 = sWorld[j][r * 4 + 1];
            float m2 = sWorld[j][r * 4 + 2];
            float m3 = sWorld[j][r * 4 + 3];
            Jout[(size_t)b * NJOINT * 3 + j * 3 + r] = m3;
            Aout[r * 4 + 0] = m0;
            Aout[r * 4 + 1] = m1;
            Aout[r * 4 + 2] = m2;
            Aout[r * 4 + 3] = m3 - (m0 * jx + m1 * jy + m2 * jz);
        }
    }
}

// ---------------------------------------------------------------------------
// Kernel C: fused shape blend + LBS, warp-independent cp.async pipeline.
// Weights live in padded shared (conflict-free) to free registers for
// occupancy; A[b] double-buffered per warp via cp.async.
// ---------------------------------------------------------------------------
__global__ void __launch_bounds__(CBLK, 8) kernelC(
    const float* __restrict__ betas,       // [B,11]
    const float* __restrict__ transl,      // [B,3]
    const float* __restrict__ shapedirs,   // [V,3,10]
    const float* __restrict__ v_template,  // [V,3]
    const float* __restrict__ W,           // [V,24]
    float* __restrict__ out)               // verts [B,V,3]
{
    __shared__ float4 sAw[CBLK / 32][2][NJOINT * 3];  // per-warp double buffer
    __shared__ float  sBT[BPB][14];                   // betas+transl per batch
    __shared__ float  sW[CBLK][25];                   // weights, pad-25 (no conflicts)

    int tid = threadIdx.x;
    int lane = tid & 31;
    int w = tid >> 5;
    int v = blockIdx.x * CBLK + tid;
    int b0 = blockIdx.y * BPB;
    bool valid = (v < NV);
    int vc = valid ? v : (NV - 1);

    // stage betas/transl for the whole batch chunk (once)
    for (int idx = tid; idx < BPB * 14; idx += CBLK) {
        int ib = idx / 14, k = idx % 14;
        sBT[ib][k] = (k < 11) ? betas[(b0 + ib) * 11 + k]
                              : transl[(b0 + ib) * 3 + (k - 11)];
    }

    // stage this thread's weights into padded shared
    {
        const float4* Wp = (const float4*)(W + (size_t)vc * NJOINT);
#pragma unroll
        for (int q = 0; q < 6; q++) {
            float4 t4 = Wp[q];
            sW[tid][4*q + 0] = t4.x;
            sW[tid][4*q + 1] = t4.y;
            sW[tid][4*q + 2] = t4.z;
            sW[tid][4*q + 3] = t4.w;
        }
    }

    // --- per-vertex constants ---
    float sd[30];
    {
        const float2* sd2 = (const float2*)(shapedirs + (size_t)vc * 30);
#pragma unroll
        for (int q = 0; q < 15; q++) { float2 t2 = sd2[q]; sd[2*q] = t2.x; sd[2*q+1] = t2.y; }
    }
    float vt0 = v_template[vc * 3 + 0];
    float vt1 = v_template[vc * 3 + 1];
    float vt2 = v_template[vc * 3 + 2];

    // --- cp.async staging: 72 float4 per batch, per warp ---
    unsigned int sbase = (unsigned int)__cvta_generic_to_shared(&sAw[w][0][0]);
    const float4* Ag = g_A4;

    {
        const float4* s0 = Ag + (size_t)b0 * 72 + lane;
        unsigned int d = sbase + lane * 16;
        cp16(d, s0); cp16(d + 32 * 16, s0 + 32);
        if (lane < 8) cp16(d + 64 * 16, s0 + 64);
        cp_commit();
        const float4* s1 = Ag + (size_t)(b0 + 1) * 72 + lane;
        unsigned int d1 = d + 72 * 16;
        cp16(d1, s1); cp16(d1 + 32 * 16, s1 + 32);
        if (lane < 8) cp16(d1 + 64 * 16, s1 + 64);
        cp_commit();
    }
    __syncthreads();   // sBT + sW visible (does not wait on cp.async)

    const float* wrow = sW[tid];

    for (int ib = 0; ib < BPB; ib++) {
        if (ib >= BPB - 2) cp_wait0(); else cp_wait1();
        __syncwarp();

        int cur = ib & 1;
        const ulonglong2* A2 = (const ulonglong2*)&sAw[w][cur][0];
        const float* BT = sBT[ib];

        // shape blend
        float be0 = BT[0];
        float q0 = vt0, q1 = vt1, q2 = vt2;
#pragma unroll
        for (int l = 0; l < NBETA; l++) {
            float bl = BT[1 + l];
            q0 = fmaf(bl, sd[l],      q0);
            q1 = fmaf(bl, sd[10 + l], q1);
            q2 = fmaf(bl, sd[20 + l], q2);
        }
        float p0 = q0 * be0, p1 = q1 * be0, p2 = q2 * be0;

        // T = sum_n w_n * A_n (packed f32x2, weights from padded shared)
        unsigned long long T0 = 0ull, T1 = 0ull, T2 = 0ull,
                           T3 = 0ull, T4 = 0ull, T5 = 0ull;
#pragma unroll
        for (int n = 0; n < NJOINT; n++) {
            float wn = wrow[n];
            unsigned long long wpk;
            asm volatile("mov.b64 %0, {%1, %1};" : "=l"(wpk) : "f"(wn));
            ulonglong2 a0 = A2[n * 3 + 0];
            ulonglong2 a1 = A2[n * 3 + 1];
            ulonglong2 a2 = A2[n * 3 + 2];
            T0 = ffma2(wpk, a0.x, T0); T1 = ffma2(wpk, a0.y, T1);
            T2 = ffma2(wpk, a1.x, T2); T3 = ffma2(wpk, a1.y, T3);
            T4 = ffma2(wpk, a2.x, T4); T5 = ffma2(wpk, a2.y, T5);
        }

        if (valid) {
            float t00, t01, t02, t03, t10, t11, t12, t13, t20, t21, t22, t23;
            f2unpack(T0, t00, t01); f2unpack(T1, t02, t03);
            f2unpack(T2, t10, t11); f2unpack(T3, t12, t13);
            f2unpack(T4, t20, t21); f2unpack(T5, t22, t23);
            size_t base = ((size_t)(b0 + ib) * NV + v) * 3;
            out[base + 0] = fmaf(t00, p0, fmaf(t01, p1, fmaf(t02, p2, t03 + BT[11])));
            out[base + 1] = fmaf(t10, p0, fmaf(t11, p1, fmaf(t12, p2, t13 + BT[12])));
            out[base + 2] = fmaf(t20, p0, fmaf(t21, p1, fmaf(t22, p2, t23 + BT[13])));
        }

        // refill the buffer we just consumed with A[b+2]
        if (ib + 2 < BPB) {
            const float4* sn = Ag + (size_t)(b0 + ib + 2) * 72 + lane;
            unsigned int d = sbase + cur * (72 * 16) + lane * 16;
            cp16(d, sn); cp16(d + 32 * 16, sn + 32);
            if (lane < 8) cp16(d + 64 * 16, sn + 64);
            cp_commit();
        }
    }
}

extern "C" void kernel_launch(void* const* d_in, const int* in_sizes, int n_in,
                              void* d_out, int out_size)
{
    const float* betas      = (const float*)d_in[0];
    const float* body_pose  = (const float*)d_in[1];
    const float* global_or  = (const float*)d_in[2];
    const float* transl     = (const float*)d_in[3];
    const float* shapedirs  = (const float*)d_in[4];
    const float* v_template = (const float*)d_in[5];
    const float* Jr         = (const float*)d_in[6];
    const float* W          = (const float*)d_in[7];
    float* out = (float*)d_out;

    kernelA<<<NBLKA, 256>>>(shapedirs, v_template, Jr);
    kernelA2<<<1, 792>>>();
    kernelB<<<BATCH, 32>>>(betas, body_pose, global_or, out);
    dim3 gridC((NV + CBLK - 1) / CBLK, NBCH);
    kernelC<<<gridC, CBLK>>>(betas, transl, shapedirs, v_template, W, out);
}

// round 6
// speedup vs baseline: 1.2075x; 1.1769x over previous
#include <cuda_runtime.h>
#include <math.h>

#define BATCH 512
#define NV 6890
#define NBETA 10
#define NJOINT 24

#define ATILE 64
#define NBLKA ((NV + ATILE - 1) / ATILE)   // 108

#define CBLK 128         // kernelC threads
#define VPT 2            // vertices per thread
#define CVERT (CBLK*VPT) // 256 vertices per block
#define NBCH 32          // kernelC batch-chunks
#define BPB (BATCH/NBCH) // 16 batches per block

#define VBLK 128         // kernelV threads
#define VB_B 64          // kernelV batches per block

__constant__ int c_parents[NJOINT] = {-1,0,0,0,1,2,3,4,5,6,7,8,9,9,9,12,13,14,16,17,18,19,20,21};

// Device scratch (no allocations allowed)
__device__ float  g_part2[NBLKA][NJOINT][33];
__device__ float  g_tot [NJOINT][33];
__device__ float4 g_A4  [BATCH * NJOINT * 3];
__device__ float  g_vs  [(size_t)BATCH * NV * 3];   // v_shaped scratch (42MB)

// ---- f32x2 packed-math helpers --------------------------------------------
__device__ __forceinline__ void f2unpack(unsigned long long v, float& lo, float& hi) {
    asm("mov.b64 {%0, %1}, %2;" : "=f"(lo), "=f"(hi) : "l"(v));
}
__device__ __forceinline__ unsigned long long ffma2(unsigned long long a,
                                                    unsigned long long b,
                                                    unsigned long long c) {
    unsigned long long d;
    asm("fma.rn.f32x2 %0, %1, %2, %3;" : "=l"(d) : "l"(a), "l"(b), "l"(c));
    return d;
}

// ---- cp.async helpers ------------------------------------------------------
__device__ __forceinline__ void cp16(unsigned int dst, const void* src) {
    asm volatile("cp.async.cg.shared.global [%0], [%1], 16;" :: "r"(dst), "l"(src) : "memory");
}
__device__ __forceinline__ void cp_commit() {
    asm volatile("cp.async.commit_group;" ::: "memory");
}
__device__ __forceinline__ void cp_wait1() {
    asm volatile("cp.async.wait_group 1;" ::: "memory");
}
__device__ __forceinline__ void cp_wait0() {
    asm volatile("cp.async.wait_group 0;" ::: "memory");
}

// ---------------------------------------------------------------------------
// Kernel A: joint-regressor partial sums per 64-vertex tile.
// ---------------------------------------------------------------------------
__global__ void __launch_bounds__(256) kernelA(
    const float* __restrict__ shapedirs,
    const float* __restrict__ v_template,
    const float* __restrict__ Jr)
{
    __shared__ float feat[ATILE][33];
    __shared__ float sJr[NJOINT][ATILE];

    int tid = threadIdx.x;
    int v0 = blockIdx.x * ATILE;

    for (int idx = tid; idx < ATILE * 33; idx += 256) {
        int v = idx / 33, i = idx % 33;
        int gv = v0 + v;
        float val = 0.f;
        if (gv < NV) val = (i < 3) ? v_template[gv * 3 + i]
                                   : shapedirs[(size_t)gv * 30 + (i - 3)];
        feat[v][i] = val;
    }
    for (int idx = tid; idx < NJOINT * ATILE; idx += 256) {
        int j = idx / ATILE, v = idx % ATILE;
        int gv = v0 + v;
        sJr[j][v] = (gv < NV) ? Jr[j * NV + gv] : 0.f;
    }
    __syncthreads();

    int warp = tid >> 5, lane = tid & 31;
#pragma unroll
    for (int jj = 0; jj < 3; jj++) {
        int j = warp * 3 + jj;
        for (int i = lane; i < 33; i += 32) {
            float a0 = 0.f, a1 = 0.f, a2 = 0.f, a3 = 0.f;
#pragma unroll
            for (int v = 0; v < ATILE; v += 4) {
                a0 = fmaf(sJr[j][v + 0], feat[v + 0][i], a0);
                a1 = fmaf(sJr[j][v + 1], feat[v + 1][i], a1);
                a2 = fmaf(sJr[j][v + 2], feat[v + 2][i], a2);
                a3 = fmaf(sJr[j][v + 3], feat[v + 3][i], a3);
            }
            g_part2[blockIdx.x][j][i] = (a0 + a1) + (a2 + a3);
        }
    }
}

__global__ void __launch_bounds__(792) kernelA2()
{
    int t = threadIdx.x;
    int j = t / 33, i33 = t % 33;
    int src;
    if (i33 % 11 == 0) src = i33 / 11;
    else { int k = i33 / 11, l = i33 % 11 - 1; src = 3 + k * 10 + l; }
    float s0 = 0.f, s1 = 0.f, s2 = 0.f, s3 = 0.f;
    for (int c = 0; c < NBLKA; c += 4) {
        s0 += g_part2[c + 0][j][src];
        s1 += g_part2[c + 1][j][src];
        s2 += g_part2[c + 2][j][src];
        s3 += g_part2[c + 3][j][src];
    }
    g_tot[j][i33] = (s0 + s1) + (s2 + s3);
}

// ---------------------------------------------------------------------------
// Kernel V: precompute v_shaped[(b,v)] = (vt + sum_l beta_l sd_l) * beta0.
// Batch-loop inverted: sd loaded once per vertex.
// ---------------------------------------------------------------------------
__global__ void __launch_bounds__(VBLK) kernelV(
    const float* __restrict__ betas,       // [B,11]
    const float* __restrict__ shapedirs,   // [V,3,10]
    const float* __restrict__ v_template)  // [V,3]
{
    __shared__ float sB[VB_B][11];
    int tid = threadIdx.x;
    int b0 = blockIdx.y * VB_B;

    for (int idx = tid; idx < VB_B * 11; idx += VBLK)
        sB[idx / 11][idx % 11] = betas[(b0 + idx / 11) * 11 + idx % 11];

    int v = blockIdx.x * VBLK + tid;
    bool valid = (v < NV);
    int vc = valid ? v : (NV - 1);

    float sd[30];
    {
        const float2* sd2 = (const float2*)(shapedirs + (size_t)vc * 30);
#pragma unroll
        for (int q = 0; q < 15; q++) { float2 t2 = sd2[q]; sd[2*q] = t2.x; sd[2*q+1] = t2.y; }
    }
    float vt0 = v_template[vc * 3 + 0];
    float vt1 = v_template[vc * 3 + 1];
    float vt2 = v_template[vc * 3 + 2];
    __syncthreads();

    if (!valid) return;
    for (int i = 0; i < VB_B; i++) {
        int b = b0 + i;
        const float* BT = sB[i];
        float be0 = BT[0];
        float q0 = vt0, q1 = vt1, q2 = vt2;
#pragma unroll
        for (int l = 0; l < NBETA; l++) {
            float bl = BT[1 + l];
            q0 = fmaf(bl, sd[l],      q0);
            q1 = fmaf(bl, sd[10 + l], q1);
            q2 = fmaf(bl, sd[20 + l], q2);
        }
        size_t base = ((size_t)b * NV + v) * 3;
        g_vs[base + 0] = q0 * be0;
        g_vs[base + 1] = q1 * be0;
        g_vs[base + 2] = q2 * be0;
    }
}

// ---------------------------------------------------------------------------
// Kernel B: per-batch joints, rodrigues, kinematic chain, A matrices.
// ---------------------------------------------------------------------------
__global__ void __launch_bounds__(32) kernelB(
    const float* __restrict__ betas,
    const float* __restrict__ body_pose,
    const float* __restrict__ global_or,
    float* __restrict__ d_out)
{
    int b = blockIdx.x;
    int lane = threadIdx.x;

    __shared__ float sB[11];
    __shared__ float sLoc[NJOINT][12];
    __shared__ float sWorld[NJOINT][12];
    __shared__ float sJ[NJOINT][3];

    if (lane < 11) sB[lane] = betas[b * 11 + lane];
    __syncwarp();

    if (lane < NJOINT) {
        int j = lane;
        float s0 = sB[0];
#pragma unroll
        for (int k = 0; k < 3; k++) {
            float val = g_tot[j][k * 11];
#pragma unroll
            for (int l = 0; l < NBETA; l++)
                val += sB[1 + l] * g_tot[j][k * 11 + 1 + l];
            sJ[j][k] = val * s0;
        }
    }
    __syncwarp();

    if (lane < NJOINT) {
        int j = lane;
        float r0, r1, r2;
        if (j == 0) {
            r0 = global_or[b * 3 + 0]; r1 = global_or[b * 3 + 1]; r2 = global_or[b * 3 + 2];
        } else {
            const float* pp = body_pose + b * 69 + (j - 1) * 3;
            r0 = pp[0]; r1 = pp[1]; r2 = pp[2];
        }
        float a0 = r0 + 1e-8f, a1 = r1 + 1e-8f, a2 = r2 + 1e-8f;
        float angle = sqrtf(a0 * a0 + a1 * a1 + a2 * a2);
        float inv = 1.0f / angle;
        float rx = r0 * inv, ry = r1 * inv, rz = r2 * inv;
        float c = cosf(angle), s = sinf(angle), t = 1.f - c;
        sLoc[j][0]  = 1.f - t * (ry * ry + rz * rz);
        sLoc[j][1]  = -s * rz + t * rx * ry;
        sLoc[j][2]  =  s * ry + t * rx * rz;
        sLoc[j][4]  =  s * rz + t * rx * ry;
        sLoc[j][5]  = 1.f - t * (rx * rx + rz * rz);
        sLoc[j][6]  = -s * rx + t * ry * rz;
        sLoc[j][8]  = -s * ry + t * rx * rz;
        sLoc[j][9]  =  s * rx + t * ry * rz;
        sLoc[j][10] = 1.f - t * (rx * rx + ry * ry);
        int p = c_parents[j];
#pragma unroll
        for (int k = 0; k < 3; k++)
            sLoc[j][k * 4 + 3] = (p < 0) ? sJ[j][k] : (sJ[j][k] - sJ[p][k]);
    }
    __syncwarp();

    if (lane < 12) sWorld[0][lane] = sLoc[0][lane];
    __syncwarp();
    for (int j = 1; j < NJOINT; j++) {
        if (lane < 12) {
            int r = lane >> 2, cc = lane & 3;
            int p = c_parents[j];
            float val = sWorld[p][r * 4 + 0] * sLoc[j][0 * 4 + cc]
                      + sWorld[p][r * 4 + 1] * sLoc[j][1 * 4 + cc]
                      + sWorld[p][r * 4 + 2] * sLoc[j][2 * 4 + cc];
            if (cc == 3) val += sWorld[p][r * 4 + 3];
            sWorld[j][lane] = val;
        }
        __syncwarp();
    }

    float* Jout = d_out + (size_t)BATCH * NV * 3;
    if (lane < NJOINT) {
        int j = lane;
        float jx = sJ[j][0], jy = sJ[j][1], jz = sJ[j][2];
        float* Aout = (float*)g_A4 + (size_t)b * 288 + j * 12;
#pragma unroll
        for (int r = 0; r < 3; r++) {
            float m0 = sWorld[j][r * 4 + 0];
            float m1 = sWorld[j][r * 4 + 1];
            float m2 = sWorld[j][r * 4 + 2];
            float m3 = sWorld[j][r * 4 + 3];
            Jout[(size_t)b * NJOINT * 3 + j * 3 + r] = m3;
            Aout[r * 4 + 0] = m0;
            Aout[r * 4 + 1] = m1;
            Aout[r * 4 + 2] = m2;
            Aout[r * 4 + 3] = m3 - (m0 * jx + m1 * jy + m2 * jz);
        }
    }
}

// ---------------------------------------------------------------------------
// Kernel C: LBS, VPT=2 vertices per thread, warp-independent cp.async pipeline.
// A reads amortized over 2 vertices; p from precomputed g_vs (L2), prefetched.
// ---------------------------------------------------------------------------
__global__ void __launch_bounds__(CBLK, 6) kernelC(
    const float* __restrict__ transl,      // [B,3]
    const float* __restrict__ W,           // [V,24]
    float* __restrict__ out)               // verts [B,V,3]
{
    __shared__ float4 sAw[CBLK / 32][2][NJOINT * 3];
    __shared__ float  sTr[BPB][3];
    __shared__ float  sW[CVERT][25];

    int tid = threadIdx.x;
    int lane = tid & 31;
    int w = tid >> 5;
    int b0 = blockIdx.y * BPB;

    int v0 = blockIdx.x * CVERT + tid;
    int v1 = v0 + CBLK;
    bool valid0 = (v0 < NV), valid1 = (v1 < NV);
    int vc0 = valid0 ? v0 : (NV - 1);
    int vc1 = valid1 ? v1 : (NV - 1);

    for (int idx = tid; idx < BPB * 3; idx += CBLK)
        sTr[idx / 3][idx % 3] = transl[(b0 + idx / 3) * 3 + idx % 3];

    // stage both vertices' weights into padded shared
    {
        const float4* Wp0 = (const float4*)(W + (size_t)vc0 * NJOINT);
        const float4* Wp1 = (const float4*)(W + (size_t)vc1 * NJOINT);
#pragma unroll
        for (int q = 0; q < 6; q++) {
            float4 t4 = Wp0[q];
            sW[tid][4*q+0] = t4.x; sW[tid][4*q+1] = t4.y;
            sW[tid][4*q+2] = t4.z; sW[tid][4*q+3] = t4.w;
            float4 u4 = Wp1[q];
            sW[tid + CBLK][4*q+0] = u4.x; sW[tid + CBLK][4*q+1] = u4.y;
            sW[tid + CBLK][4*q+2] = u4.z; sW[tid + CBLK][4*q+3] = u4.w;
        }
    }

    // --- cp.async staging of A ---
    unsigned int sbase = (unsigned int)__cvta_generic_to_shared(&sAw[w][0][0]);
    const float4* Ag = g_A4;
    {
        const float4* s0 = Ag + (size_t)b0 * 72 + lane;
        unsigned int d = sbase + lane * 16;
        cp16(d, s0); cp16(d + 32 * 16, s0 + 32);
        if (lane < 8) cp16(d + 64 * 16, s0 + 64);
        cp_commit();
        const float4* s1 = Ag + (size_t)(b0 + 1) * 72 + lane;
        unsigned int d1 = d + 72 * 16;
        cp16(d1, s1); cp16(d1 + 32 * 16, s1 + 32);
        if (lane < 8) cp16(d1 + 64 * 16, s1 + 64);
        cp_commit();
    }
    __syncthreads();   // sW/sTr visible

    // p prefetch for ib=0
    float pA0, pA1, pA2, pB0, pB1, pB2;
    {
        const float* p = g_vs + ((size_t)b0 * NV + vc0) * 3;
        pA0 = p[0]; pA1 = p[1]; pA2 = p[2];
        const float* q = g_vs + ((size_t)b0 * NV + vc1) * 3;
        pB0 = q[0]; pB1 = q[1]; pB2 = q[2];
    }

    const float* wr0 = sW[tid];
    const float* wr1 = sW[tid + CBLK];

    for (int ib = 0; ib < BPB; ib++) {
        if (ib >= BPB - 2) cp_wait0(); else cp_wait1();
        __syncwarp();

        int cur = ib & 1;
        const ulonglong2* A2 = (const ulonglong2*)&sAw[w][cur][0];

        unsigned long long TA0=0,TA1=0,TA2=0,TA3=0,TA4=0,TA5=0;
        unsigned long long TB0=0,TB1=0,TB2=0,TB3=0,TB4=0,TB5=0;
#pragma unroll
        for (int n = 0; n < NJOINT; n++) {
            float wA = wr0[n], wB = wr1[n];
            unsigned long long wpA, wpB;
            asm volatile("mov.b64 %0, {%1, %1};" : "=l"(wpA) : "f"(wA));
            asm volatile("mov.b64 %0, {%1, %1};" : "=l"(wpB) : "f"(wB));
            ulonglong2 a0 = A2[n * 3 + 0];
            ulonglong2 a1 = A2[n * 3 + 1];
            ulonglong2 a2 = A2[n * 3 + 2];
            TA0 = ffma2(wpA, a0.x, TA0); TB0 = ffma2(wpB, a0.x, TB0);
            TA1 = ffma2(wpA, a0.y, TA1); TB1 = ffma2(wpB, a0.y, TB1);
            TA2 = ffma2(wpA, a1.x, TA2); TB2 = ffma2(wpB, a1.x, TB2);
            TA3 = ffma2(wpA, a1.y, TA3); TB3 = ffma2(wpB, a1.y, TB3);
            TA4 = ffma2(wpA, a2.x, TA4); TB4 = ffma2(wpB, a2.x, TB4);
            TA5 = ffma2(wpA, a2.y, TA5); TB5 = ffma2(wpB, a2.y, TB5);
        }

        int b = b0 + ib;
        float tr0 = sTr[ib][0], tr1 = sTr[ib][1], tr2 = sTr[ib][2];

        if (valid0) {
            float t00,t01,t02,t03,t10,t11,t12,t13,t20,t21,t22,t23;
            f2unpack(TA0,t00,t01); f2unpack(TA1,t02,t03);
            f2unpack(TA2,t10,t11); f2unpack(TA3,t12,t13);
            f2unpack(TA4,t20,t21); f2unpack(TA5,t22,t23);
            size_t base = ((size_t)b * NV + v0) * 3;
            out[base+0] = fmaf(t00,pA0, fmaf(t01,pA1, fmaf(t02,pA2, t03 + tr0)));
            out[base+1] = fmaf(t10,pA0, fmaf(t11,pA1, fmaf(t12,pA2, t13 + tr1)));
            out[base+2] = fmaf(t20,pA0, fmaf(t21,pA1, fmaf(t22,pA2, t23 + tr2)));
        }
        if (valid1) {
            float t00,t01,t02,t03,t10,t11,t12,t13,t20,t21,t22,t23;
            f2unpack(TB0,t00,t01); f2unpack(TB1,t02,t03);
            f2unpack(TB2,t10,t11); f2unpack(TB3,t12,t13);
            f2unpack(TB4,t20,t21); f2unpack(TB5,t22,t23);
            size_t base = ((size_t)b * NV + v1) * 3;
            out[base+0] = fmaf(t00,pB0, fmaf(t01,pB1, fmaf(t02,pB2, t03 + tr0)));
            out[base+1] = fmaf(t10,pB0, fmaf(t11,pB1, fmaf(t12,pB2, t13 + tr1)));
            out[base+2] = fmaf(t20,pB0, fmaf(t21,pB1, fmaf(t22,pB2, t23 + tr2)));
        }

        // prefetch p for next batch
        if (ib + 1 < BPB) {
            const float* p = g_vs + ((size_t)(b + 1) * NV + vc0) * 3;
            pA0 = p[0]; pA1 = p[1]; pA2 = p[2];
            const float* q = g_vs + ((size_t)(b + 1) * NV + vc1) * 3;
            pB0 = q[0]; pB1 = q[1]; pB2 = q[2];
        }

        // refill consumed A buffer with batch b+2
        if (ib + 2 < BPB) {
            const float4* sn = Ag + (size_t)(b + 2) * 72 + lane;
            unsigned int d = sbase + cur * (72 * 16) + lane * 16;
            cp16(d, sn); cp16(d + 32 * 16, sn + 32);
            if (lane < 8) cp16(d + 64 * 16, sn + 64);
            cp_commit();
        }
    }
}

extern "C" void kernel_launch(void* const* d_in, const int* in_sizes, int n_in,
                              void* d_out, int out_size)
{
    const float* betas      = (const float*)d_in[0];
    const float* body_pose  = (const float*)d_in[1];
    const float* global_or  = (const float*)d_in[2];
    const float* transl     = (const float*)d_in[3];
    const float* shapedirs  = (const float*)d_in[4];
    const float* v_template = (const float*)d_in[5];
    const float* Jr         = (const float*)d_in[6];
    const float* W          = (const float*)d_in[7];
    float* out = (float*)d_out;

    kernelA<<<NBLKA, 256>>>(shapedirs, v_template, Jr);
    dim3 gridV((NV + VBLK - 1) / VBLK, BATCH / VB_B);
    kernelV<<<gridV, VBLK>>>(betas, shapedirs, v_template);
    kernelA2<<<1, 792>>>();
    kernelB<<<BATCH, 32>>>(betas, body_pose, global_or, out);
    dim3 gridC((NV + CVERT - 1) / CVERT, NBCH);
    kernelC<<<gridC, CBLK>>>(transl, W, out);
}